// round 13
// baseline (speedup 1.0000x reference)
#include <cuda_runtime.h>
#include <cuda_bf16.h>
#include <math.h>
#include <stdint.h>

// Problem constants: B=2, T=2048, C=512, H=8, D=64, K=4
#define GAMMA 2.5f
#define TOPK 4
#define RHO 0.085f
#define TAU_CLIP 5.0f
#define NUM_HEADS 8

#define MAX_BT   4096
#define MAX_C    512
#define MAX_3C   1536

// ------------------------- scratch (device globals) -------------------------
__device__ float          g_qkv[MAX_BT * MAX_3C];
__device__ __nv_bfloat16  g_xh[MAX_BT * MAX_C];
__device__ __nv_bfloat16  g_xl[MAX_BT * MAX_C];
__device__ __nv_bfloat16  g_aoh[MAX_BT * MAX_C];
__device__ __nv_bfloat16  g_aol[MAX_BT * MAX_C];
__device__ __nv_bfloat16  g_wqh[MAX_3C * MAX_C];
__device__ __nv_bfloat16  g_wql[MAX_3C * MAX_C];
__device__ __nv_bfloat16  g_wph[MAX_C * MAX_C];
__device__ __nv_bfloat16  g_wpl[MAX_C * MAX_C];
__device__ int   g_topk[MAX_BT * TOPK];
__device__ float g_sig3[MAX_BT * TOPK];
__device__ float g_rowsum[MAX_BT];
__device__ float g_sigsum[MAX_BT];

// ========================= helpers ==========================================
__device__ __forceinline__ uint32_t smem_u32(const void* p) {
    uint32_t a;
    asm("{ .reg .u64 t; cvta.to.shared.u64 t, %1; cvt.u32.u64 %0, t; }"
        : "=r"(a) : "l"(p));
    return a;
}

__device__ __forceinline__ void ldsm4(uint32_t& r0, uint32_t& r1,
                                      uint32_t& r2, uint32_t& r3, uint32_t a) {
    asm volatile("ldmatrix.sync.aligned.m8n8.x4.shared.b16 {%0,%1,%2,%3}, [%4];"
                 : "=r"(r0), "=r"(r1), "=r"(r2), "=r"(r3) : "r"(a));
}

__device__ __forceinline__ void mma16816(float* d, const uint32_t* a,
                                         const uint32_t* b) {
    asm volatile(
        "mma.sync.aligned.m16n8k16.row.col.f32.bf16.bf16.f32 "
        "{%0,%1,%2,%3},{%4,%5,%6,%7},{%8,%9},{%0,%1,%2,%3};"
        : "+f"(d[0]), "+f"(d[1]), "+f"(d[2]), "+f"(d[3])
        : "r"(a[0]), "r"(a[1]), "r"(a[2]), "r"(a[3]), "r"(b[0]), "r"(b[1]));
}

__device__ __forceinline__ void cp16(uint32_t dst, const void* src) {
    asm volatile("cp.async.cg.shared.global [%0], [%1], 16;"
                 :: "r"(dst), "l"(src));
}

__device__ __forceinline__ uint32_t sw_off(int row, int kc) {
    return (uint32_t)(row * 64 + ((kc ^ ((row >> 1) & 3)) << 4));
}

// ========================= bf16x3 HMMA GEMM =================================
// Tile 128x128x32, 8 warps (warp tile 64x32), 3-stage cp.async pipeline.
// Reordered frag loads: bh+bl early, al under the ah*bl MMAs.
#define BKQ 32
#define NSTAGE 3
#define STAGE_BYTES 32768
#define OFF_AH 0
#define OFF_AL 8192
#define OFF_BH 16384
#define OFF_BL 24576
#define GEMM_SMEM (NSTAGE * STAGE_BYTES)

__global__ __launch_bounds__(256, 2) void gemm_bf16x3_kernel(
    const __nv_bfloat16* __restrict__ Ah, const __nv_bfloat16* __restrict__ Al,
    const __nv_bfloat16* __restrict__ Bh, const __nv_bfloat16* __restrict__ Bl,
    const float* __restrict__ bias, float* __restrict__ Cout,
    int M, int N, int K)
{
    extern __shared__ char smem[];
    const uint32_t sb = smem_u32(smem);
    const int tid  = threadIdx.x;
    const int brow = blockIdx.y * 128;
    const int bcol = blockIdx.x * 128;
    const int wid  = tid >> 5, lane = tid & 31;
    const int wm   = wid >> 2, wn = wid & 3;

    const int lr = tid >> 2, lc = tid & 3;

    const int a_row = (lane & 7) + ((lane >> 3) & 1) * 8;
    const int a_kc  = lane >> 4;
    const int b_row = (lane & 7) + ((lane >> 4) & 1) * 8;
    const int b_kc  = (lane >> 3) & 1;

    float acc[4][4][4];
#pragma unroll
    for (int i = 0; i < 4; i++)
#pragma unroll
        for (int j = 0; j < 4; j++)
#pragma unroll
            for (int q = 0; q < 4; q++) acc[i][j][q] = 0.0f;

    auto issue_stage = [&](int stage, int k0) {
        uint32_t st = sb + stage * STAGE_BYTES;
#pragma unroll
        for (int p = 0; p < 2; ++p) {
            int r = lr + p * 64;
            uint32_t o = sw_off(r, lc);
            size_t ga = (size_t)(brow + r) * K + k0 + lc * 8;
            size_t gb = (size_t)(bcol + r) * K + k0 + lc * 8;
            cp16(st + OFF_AH + o, Ah + ga);
            cp16(st + OFF_AL + o, Al + ga);
            cp16(st + OFF_BH + o, Bh + gb);
            cp16(st + OFF_BL + o, Bl + gb);
        }
        asm volatile("cp.async.commit_group;");
    };

    const int niter = K / BKQ;
    issue_stage(0, 0);
    if (niter > 1) issue_stage(1, BKQ);

    for (int it = 0; it < niter; ++it) {
        if (it + 1 < niter) asm volatile("cp.async.wait_group 1;");
        else                asm volatile("cp.async.wait_group 0;");
        __syncthreads();
        if (it + 2 < niter) issue_stage((it + 2) % NSTAGE, (it + 2) * BKQ);

        const uint32_t st = sb + (it % NSTAGE) * STAGE_BYTES;

#pragma unroll
        for (int ks = 0; ks < 2; ++ks) {
            uint32_t ah[4][4], al[4][4], bh[4][2], bl[4][2];
            // --- all B frags first (long load->use distance for bl) ---
#pragma unroll
            for (int pr = 0; pr < 2; ++pr) {
                int row = wn * 32 + pr * 16 + b_row;
                uint32_t adh = st + OFF_BH + sw_off(row, ks * 2 + b_kc);
                ldsm4(bh[2 * pr][0], bh[2 * pr][1],
                      bh[2 * pr + 1][0], bh[2 * pr + 1][1], adh);
            }
#pragma unroll
            for (int pr = 0; pr < 2; ++pr) {
                int row = wn * 32 + pr * 16 + b_row;
                uint32_t adl = st + OFF_BL + sw_off(row, ks * 2 + b_kc);
                ldsm4(bl[2 * pr][0], bl[2 * pr][1],
                      bl[2 * pr + 1][0], bl[2 * pr + 1][1], adl);
            }
            // --- A hi ---
#pragma unroll
            for (int mt = 0; mt < 4; ++mt) {
                int row = wm * 64 + mt * 16 + a_row;
                uint32_t ad = st + OFF_AH + sw_off(row, ks * 2 + a_kc);
                ldsm4(ah[mt][0], ah[mt][1], ah[mt][2], ah[mt][3], ad);
            }
            // hh MMAs
#pragma unroll
            for (int mt = 0; mt < 4; ++mt)
#pragma unroll
                for (int nt = 0; nt < 4; ++nt)
                    mma16816(acc[mt][nt], ah[mt], bh[nt]);
            // --- A lo load hidden under ah*bl MMAs ---
#pragma unroll
            for (int mt = 0; mt < 4; ++mt) {
                int row = wm * 64 + mt * 16 + a_row;
                uint32_t ad = st + OFF_AL + sw_off(row, ks * 2 + a_kc);
                ldsm4(al[mt][0], al[mt][1], al[mt][2], al[mt][3], ad);
            }
            // hl MMAs (ah * bl)
#pragma unroll
            for (int mt = 0; mt < 4; ++mt)
#pragma unroll
                for (int nt = 0; nt < 4; ++nt)
                    mma16816(acc[mt][nt], ah[mt], bl[nt]);
            // lh MMAs (al * bh)
#pragma unroll
            for (int mt = 0; mt < 4; ++mt)
#pragma unroll
                for (int nt = 0; nt < 4; ++nt)
                    mma16816(acc[mt][nt], al[mt], bh[nt]);
        }
    }

    const int gid = lane >> 2, tig = lane & 3;
#pragma unroll
    for (int mt = 0; mt < 4; ++mt) {
#pragma unroll
        for (int nt = 0; nt < 4; ++nt) {
            int row = brow + wm * 64 + mt * 16 + gid;
            int col = bcol + wn * 32 + nt * 8 + tig * 2;
            float b0 = bias[col], b1 = bias[col + 1];
            float2 v0 = make_float2(acc[mt][nt][0] + b0, acc[mt][nt][1] + b1);
            float2 v1 = make_float2(acc[mt][nt][2] + b0, acc[mt][nt][3] + b1);
            *(float2*)(Cout + (size_t)row * N + col) = v0;
            *(float2*)(Cout + (size_t)(row + 8) * N + col) = v1;
        }
    }
}

// ========================= fp32 -> bf16 hi/lo split =========================
__global__ void split_kernel(const float* __restrict__ in,
                             __nv_bfloat16* __restrict__ h,
                             __nv_bfloat16* __restrict__ l, int n)
{
    int i = blockIdx.x * blockDim.x + threadIdx.x;
    if (i < n) {
        float v = in[i];
        __nv_bfloat16 hh = __float2bfloat16(v);
        h[i] = hh;
        l[i] = __float2bfloat16(v - __bfloat162float(hh));
    }
}

// ============== weight transpose + split: W[K][N] -> Wt[N][K] hi/lo =========
__global__ void wsplit_t_kernel(const float* __restrict__ W,
                                __nv_bfloat16* __restrict__ Wth,
                                __nv_bfloat16* __restrict__ Wtl, int K, int N)
{
    __shared__ float t[32][33];
    const int n0 = blockIdx.x * 32, k0 = blockIdx.y * 32;
    const int tx = threadIdx.x, ty = threadIdx.y;
#pragma unroll
    for (int j = 0; j < 4; ++j)
        t[ty + j * 8][tx] = W[(size_t)(k0 + ty + j * 8) * N + n0 + tx];
    __syncthreads();
#pragma unroll
    for (int j = 0; j < 4; ++j) {
        int nn = ty + j * 8;
        float v = t[tx][nn];
        __nv_bfloat16 hh = __float2bfloat16(v);
        size_t o = (size_t)(n0 + nn) * K + k0 + tx;
        Wth[o] = hh;
        Wtl[o] = __float2bfloat16(v - __bfloat162float(hh));
    }
}

// ============ single-pass top-4 + rowsum (branchless scalar regs) ===========
__device__ __forceinline__ void ins4(float& v0, int& i0, float& v1, int& i1,
                                     float& v2, int& i2, float& v3, int& i3,
                                     float val, int idx)
{
    bool b0 = (val > v0) | ((val == v0) & (idx < i0));
    bool b1 = (val > v1) | ((val == v1) & (idx < i1));
    bool b2 = (val > v2) | ((val == v2) & (idx < i2));
    bool b3 = (val > v3) | ((val == v3) & (idx < i3));
    v3 = b3 ? (b2 ? v2 : val) : v3;  i3 = b3 ? (b2 ? i2 : idx) : i3;
    v2 = b2 ? (b1 ? v1 : val) : v2;  i2 = b2 ? (b1 ? i1 : idx) : i2;
    v1 = b1 ? (b0 ? v0 : val) : v1;  i1 = b1 ? (b0 ? i0 : idx) : i1;
    v0 = b0 ? val : v0;              i0 = b0 ? idx : i0;
}

__global__ void topk_kernel(const float* __restrict__ tau,
                            int* __restrict__ topk,
                            float* __restrict__ rowsum, int T)
{
    const int row  = blockIdx.x;
    const int tid  = threadIdx.x;
    const int lane = tid & 31, wid = tid >> 5;
    const float* tr = tau + (size_t)row * T;

    float v0 = -INFINITY, v1 = -INFINITY, v2 = -INFINITY, v3 = -INFINITY;
    int   i0 = 0x7FFFFFFF, i1 = 0x7FFFFFFF, i2 = 0x7FFFFFFF, i3 = 0x7FFFFFFF;
    float s = 0.0f;

    for (int i = tid; i < T; i += 256) {
        float val = tr[i];
        s += val;
        ins4(v0, i0, v1, i1, v2, i2, v3, i3, val, i);
    }

#pragma unroll
    for (int off = 16; off > 0; off >>= 1) {
        s += __shfl_xor_sync(0xFFFFFFFFu, s, off);
        float w0 = __shfl_xor_sync(0xFFFFFFFFu, v0, off);
        int   j0 = __shfl_xor_sync(0xFFFFFFFFu, i0, off);
        float w1 = __shfl_xor_sync(0xFFFFFFFFu, v1, off);
        int   j1 = __shfl_xor_sync(0xFFFFFFFFu, i1, off);
        float w2 = __shfl_xor_sync(0xFFFFFFFFu, v2, off);
        int   j2 = __shfl_xor_sync(0xFFFFFFFFu, i2, off);
        float w3 = __shfl_xor_sync(0xFFFFFFFFu, v3, off);
        int   j3 = __shfl_xor_sync(0xFFFFFFFFu, i3, off);
        ins4(v0, i0, v1, i1, v2, i2, v3, i3, w0, j0);
        ins4(v0, i0, v1, i1, v2, i2, v3, i3, w1, j1);
        ins4(v0, i0, v1, i1, v2, i2, v3, i3, w2, j2);
        ins4(v0, i0, v1, i1, v2, i2, v3, i3, w3, j3);
    }

    __shared__ float wv[8][4];
    __shared__ int   wi[8][4];
    __shared__ float ws[8];
    if (lane == 0) {
        wv[wid][0] = v0; wv[wid][1] = v1; wv[wid][2] = v2; wv[wid][3] = v3;
        wi[wid][0] = i0; wi[wid][1] = i1; wi[wid][2] = i2; wi[wid][3] = i3;
        ws[wid] = s;
    }
    __syncthreads();

    if (tid == 0) {
        float sum = ws[0];
#pragma unroll
        for (int w = 1; w < 8; ++w) {
            sum += ws[w];
            ins4(v0, i0, v1, i1, v2, i2, v3, i3, wv[w][0], wi[w][0]);
            ins4(v0, i0, v1, i1, v2, i2, v3, i3, wv[w][1], wi[w][1]);
            ins4(v0, i0, v1, i1, v2, i2, v3, i3, wv[w][2], wi[w][2]);
            ins4(v0, i0, v1, i1, v2, i2, v3, i3, wv[w][3], wi[w][3]);
        }
        rowsum[row] = sum;
        int4 r = make_int4(i0, i1, i2, i3);
        *(int4*)(topk + row * TOPK) = r;
    }
}

// ================= sparse attention core (float2 vectorized) ================
// lane l handles dims 2l, 2l+1 of its head (64 dims / 32 lanes).
__global__ void attn_kernel(const float* __restrict__ qkv,
                            const float* __restrict__ tau,
                            const int* __restrict__ topk,
                            __nv_bfloat16* __restrict__ aoh,
                            __nv_bfloat16* __restrict__ aol,
                            float* __restrict__ sig3,
                            float* __restrict__ sigsum,
                            int T, int C)
{
    const int row = blockIdx.x;
    const int b   = row / T;
    const int h   = threadIdx.x >> 5;
    const int l   = threadIdx.x & 31;
    const int C3  = 3 * C;

    __shared__ int   sidx[TOPK];
    __shared__ float sbias[TOPK];
    __shared__ float satt[NUM_HEADS][TOPK];

    if (threadIdx.x < TOPK) {
        int id = topk[row * TOPK + threadIdx.x];
        sidx[threadIdx.x]  = id;
        sbias[threadIdx.x] = GAMMA * logf(tau[(size_t)row * T + id] + 1e-8f);
    }
    __syncthreads();

    const float* qrow = qkv + (size_t)row * C3 + h * 64;
    const float2 q01 = *(const float2*)(qrow + 2 * l);

    float logit[TOPK];
#pragma unroll
    for (int j = 0; j < TOPK; j++) {
        const float* krow = qkv + (size_t)(b * T + sidx[j]) * C3 + C + h * 64;
        float2 kk = *(const float2*)(krow + 2 * l);
        float p = q01.x * kk.x + q01.y * kk.y;
#pragma unroll
        for (int off = 16; off > 0; off >>= 1)
            p += __shfl_xor_sync(0xFFFFFFFFu, p, off);
        logit[j] = p * 0.125f + sbias[j];
    }

    float m = fmaxf(fmaxf(logit[0], logit[1]), fmaxf(logit[2], logit[3]));
    float e[TOPK], den = 0.0f;
#pragma unroll
    for (int j = 0; j < TOPK; j++) { e[j] = expf(logit[j] - m); den += e[j]; }
    float inv = 1.0f / den;
    float a[TOPK];
#pragma unroll
    for (int j = 0; j < TOPK; j++) a[j] = e[j] * inv;

    // out dims 2l, 2l+1
    float o0 = 0.0f, o1 = 0.0f;
#pragma unroll
    for (int j = 0; j < TOPK; j++) {
        const float* vrow = qkv + (size_t)(b * T + sidx[j]) * C3 + 2 * C + h * 64;
        float2 vv = *(const float2*)(vrow + 2 * l);
        o0 = fmaf(a[j], vv.x, o0);
        o1 = fmaf(a[j], vv.y, o1);
    }
    {
        size_t base = (size_t)row * C + h * 64 + 2 * l;
        __nv_bfloat16 h0 = __float2bfloat16(o0);
        __nv_bfloat16 h1 = __float2bfloat16(o1);
        __nv_bfloat162 hv; hv.x = h0; hv.y = h1;
        *(__nv_bfloat162*)(aoh + base) = hv;
        __nv_bfloat162 lv;
        lv.x = __float2bfloat16(o0 - __bfloat162float(h0));
        lv.y = __float2bfloat16(o1 - __bfloat162float(h1));
        *(__nv_bfloat162*)(aol + base) = lv;
    }

    if (l == 0) {
#pragma unroll
        for (int j = 0; j < TOPK; j++) satt[h][j] = a[j];
    }
    __syncthreads();

    if (threadIdx.x == 0) {
        float ss = 0.0f;
#pragma unroll
        for (int j = 0; j < TOPK; j++) {
            float sgn = 0.0f;
#pragma unroll
            for (int hh = 0; hh < NUM_HEADS; hh++) sgn += satt[hh][j];
            sgn *= (1.0f / NUM_HEADS);
            float s3 = sgn * sgn * sgn;
            sig3[row * TOPK + j] = s3;
            ss += s3;
        }
        sigsum[row] = ss;
    }
}

// ========================= tau EMA: branchless stream + fixup ===============
__global__ void tau_main_kernel(const float* __restrict__ tau,
                                const float* __restrict__ rowsum,
                                const float* __restrict__ sigsum,
                                float* __restrict__ tau_out, int T)
{
    const int row = blockIdx.x;
    const float keep = 1.0f - RHO;
    const float ki = keep / (keep * rowsum[row] + sigsum[row] + 1e-8f);
    const float4* tr = (const float4*)(tau + (size_t)row * T);
    float4* to = (float4*)(tau_out + (size_t)row * T);
    const int n4 = T >> 2;
    for (int i = threadIdx.x; i < n4; i += blockDim.x) {
        float4 v = tr[i];
        v.x = fminf(v.x * ki, TAU_CLIP);
        v.y = fminf(v.y * ki, TAU_CLIP);
        v.z = fminf(v.z * ki, TAU_CLIP);
        v.w = fminf(v.w * ki, TAU_CLIP);
        to[i] = v;
    }
}

__global__ void tau_fix_kernel(const float* __restrict__ tau,
                               const int* __restrict__ topk,
                               const float* __restrict__ sig3,
                               const float* __restrict__ rowsum,
                               const float* __restrict__ sigsum,
                               float* __restrict__ tau_out, int T, int BT)
{
    int g = blockIdx.x * blockDim.x + threadIdx.x;
    int row = g >> 2, j = g & 3;
    if (row >= BT) return;
    const float keep = 1.0f - RHO;
    const float inv = 1.0f / (keep * rowsum[row] + sigsum[row] + 1e-8f);
    int s = topk[row * TOPK + j];
    float v = keep * tau[(size_t)row * T + s] + sig3[row * TOPK + j];
    tau_out[(size_t)row * T + s] = fminf(v * inv, TAU_CLIP);
}

// ========================= launch ===========================================
extern "C" void kernel_launch(void* const* d_in, const int* in_sizes, int n_in,
                              void* d_out, int out_size)
{
    const float* x     = (const float*)d_in[0];
    const float* tau   = (const float*)d_in[1];
    const float* Wqkv  = (const float*)d_in[2];
    const float* bqkv  = (const float*)d_in[3];
    const float* Wproj = (const float*)d_in[4];
    const float* bproj = (const float*)d_in[5];

    const int C  = in_sizes[5];                 // 512
    const int BT = in_sizes[0] / C;             // 4096
    const int T  = in_sizes[1] / BT;            // 2048
    const int C3 = 3 * C;

    float* out_main = (float*)d_out;
    float* tau_out  = out_main + (size_t)BT * C;

    float* qkv;            cudaGetSymbolAddress((void**)&qkv,  g_qkv);
    __nv_bfloat16 *xh, *xl, *aoh, *aol, *wqh, *wql, *wph, *wpl;
    cudaGetSymbolAddress((void**)&xh,  g_xh);
    cudaGetSymbolAddress((void**)&xl,  g_xl);
    cudaGetSymbolAddress((void**)&aoh, g_aoh);
    cudaGetSymbolAddress((void**)&aol, g_aol);
    cudaGetSymbolAddress((void**)&wqh, g_wqh);
    cudaGetSymbolAddress((void**)&wql, g_wql);
    cudaGetSymbolAddress((void**)&wph, g_wph);
    cudaGetSymbolAddress((void**)&wpl, g_wpl);
    int*   topk;   cudaGetSymbolAddress((void**)&topk,   g_topk);
    float* sig3;   cudaGetSymbolAddress((void**)&sig3,   g_sig3);
    float* rowsum; cudaGetSymbolAddress((void**)&rowsum, g_rowsum);
    float* sigsum; cudaGetSymbolAddress((void**)&sigsum, g_sigsum);

    // one-time setup: smem attribute + side stream + fork/join events
    static cudaStream_t s1 = nullptr;
    static cudaEvent_t evFork = nullptr, evSide = nullptr,
                       evAttn = nullptr, evTau = nullptr;
    if (s1 == nullptr) {
        cudaFuncSetAttribute(gemm_bf16x3_kernel,
                             cudaFuncAttributeMaxDynamicSharedMemorySize,
                             GEMM_SMEM);
        cudaStreamCreateWithFlags(&s1, cudaStreamNonBlocking);
        cudaEventCreateWithFlags(&evFork, cudaEventDisableTiming);
        cudaEventCreateWithFlags(&evSide, cudaEventDisableTiming);
        cudaEventCreateWithFlags(&evAttn, cudaEventDisableTiming);
        cudaEventCreateWithFlags(&evTau,  cudaEventDisableTiming);
    }

    // ---- fork: side stream runs topk + Wproj split, overlapping qkv GEMM ----
    cudaEventRecord(evFork, 0);
    cudaStreamWaitEvent(s1, evFork, 0);
    topk_kernel<<<BT, 256, 0, s1>>>(tau, topk, rowsum, T);
    {
        dim3 tb(32, 8);
        wsplit_t_kernel<<<dim3(C / 32, C / 32), tb, 0, s1>>>(Wproj, wph, wpl, C, C);
    }
    cudaEventRecord(evSide, s1);

    // ---- main stream: operand prep + qkv GEMM ----
    {
        int n = BT * C;
        split_kernel<<<(n + 255) / 256, 256>>>(x, xh, xl, n);
        dim3 tb(32, 8);
        wsplit_t_kernel<<<dim3(C3 / 32, C / 32), tb>>>(Wqkv, wqh, wql, C, C3);
    }
    {
        dim3 grid(C3 / 128, BT / 128);
        gemm_bf16x3_kernel<<<grid, 256, GEMM_SMEM>>>(xh, xl, wqh, wql,
                                                     bqkv, qkv, BT, C3, C);
    }

    // ---- join: attention needs qkv (main) + topk (side) ----
    cudaStreamWaitEvent(0, evSide, 0);
    attn_kernel<<<BT, 256>>>(qkv, tau, topk, aoh, aol, sig3, sigsum, T, C);
    cudaEventRecord(evAttn, 0);

    // ---- fork again: tau update (DRAM-bound) overlaps proj GEMM (tensor) ----
    cudaStreamWaitEvent(s1, evAttn, 0);
    tau_main_kernel<<<BT, 256, 0, s1>>>(tau, rowsum, sigsum, tau_out, T);
    {
        int tot = BT * TOPK;
        tau_fix_kernel<<<(tot + 255) / 256, 256, 0, s1>>>(tau, topk, sig3,
                                                          rowsum, sigsum,
                                                          tau_out, T, BT);
    }
    cudaEventRecord(evTau, s1);

    // ---- main stream: proj GEMM ----
    {
        dim3 grid(C / 128, BT / 128);
        gemm_bf16x3_kernel<<<grid, 256, GEMM_SMEM>>>(aoh, aol, wph, wpl,
                                                     bproj, out_main, BT, C, C);
    }
    // ---- final join so all captured work ends on the origin stream ----
    cudaStreamWaitEvent(0, evTau, 0);
}

// round 14
// speedup vs baseline: 1.0571x; 1.0571x over previous
#include <cuda_runtime.h>
#include <cuda_bf16.h>
#include <math.h>
#include <stdint.h>

// Problem constants: B=2, T=2048, C=512, H=8, D=64, K=4
#define GAMMA 2.5f
#define TOPK 4
#define RHO 0.085f
#define TAU_CLIP 5.0f
#define NUM_HEADS 8

#define MAX_BT   4096
#define MAX_C    512
#define MAX_3C   1536

// ------------------------- scratch (device globals) -------------------------
__device__ float          g_qkv[MAX_BT * MAX_3C];
__device__ __nv_bfloat16  g_xh[MAX_BT * MAX_C];
__device__ __nv_bfloat16  g_xl[MAX_BT * MAX_C];
__device__ __nv_bfloat16  g_aoh[MAX_BT * MAX_C];
__device__ __nv_bfloat16  g_aol[MAX_BT * MAX_C];
__device__ __nv_bfloat16  g_wqh[MAX_3C * MAX_C];
__device__ __nv_bfloat16  g_wql[MAX_3C * MAX_C];
__device__ __nv_bfloat16  g_wph[MAX_C * MAX_C];
__device__ __nv_bfloat16  g_wpl[MAX_C * MAX_C];
__device__ int   g_topk[MAX_BT * TOPK];
__device__ float g_sig3[MAX_BT * TOPK];
__device__ float g_rowsum[MAX_BT];
__device__ float g_sigsum[MAX_BT];

// ========================= helpers ==========================================
__device__ __forceinline__ uint32_t smem_u32(const void* p) {
    uint32_t a;
    asm("{ .reg .u64 t; cvta.to.shared.u64 t, %1; cvt.u32.u64 %0, t; }"
        : "=r"(a) : "l"(p));
    return a;
}

__device__ __forceinline__ void ldsm4(uint32_t& r0, uint32_t& r1,
                                      uint32_t& r2, uint32_t& r3, uint32_t a) {
    asm volatile("ldmatrix.sync.aligned.m8n8.x4.shared.b16 {%0,%1,%2,%3}, [%4];"
                 : "=r"(r0), "=r"(r1), "=r"(r2), "=r"(r3) : "r"(a));
}

__device__ __forceinline__ void mma16816(float* d, const uint32_t* a,
                                         const uint32_t* b) {
    asm volatile(
        "mma.sync.aligned.m16n8k16.row.col.f32.bf16.bf16.f32 "
        "{%0,%1,%2,%3},{%4,%5,%6,%7},{%8,%9},{%0,%1,%2,%3};"
        : "+f"(d[0]), "+f"(d[1]), "+f"(d[2]), "+f"(d[3])
        : "r"(a[0]), "r"(a[1]), "r"(a[2]), "r"(a[3]), "r"(b[0]), "r"(b[1]));
}

__device__ __forceinline__ void cp16(uint32_t dst, const void* src) {
    asm volatile("cp.async.cg.shared.global [%0], [%1], 16;"
                 :: "r"(dst), "l"(src));
}

__device__ __forceinline__ uint32_t sw_off(int row, int kc) {
    return (uint32_t)(row * 64 + ((kc ^ ((row >> 1) & 3)) << 4));
}

// ========================= bf16x3 HMMA GEMM =================================
// ROUND-12 ORDERING RESTORED (known-good 144.4us config):
// bh -> ah -> MMA(hh) -> al -> MMA(al*bh) -> bl -> MMA(ah*bl).
// Tile 128x128x32, 8 warps (warp tile 64x32), 3-stage cp.async pipeline.
#define BKQ 32
#define NSTAGE 3
#define STAGE_BYTES 32768
#define OFF_AH 0
#define OFF_AL 8192
#define OFF_BH 16384
#define OFF_BL 24576
#define GEMM_SMEM (NSTAGE * STAGE_BYTES)

__global__ __launch_bounds__(256, 2) void gemm_bf16x3_kernel(
    const __nv_bfloat16* __restrict__ Ah, const __nv_bfloat16* __restrict__ Al,
    const __nv_bfloat16* __restrict__ Bh, const __nv_bfloat16* __restrict__ Bl,
    const float* __restrict__ bias, float* __restrict__ Cout,
    int M, int N, int K)
{
    extern __shared__ char smem[];
    const uint32_t sb = smem_u32(smem);
    const int tid  = threadIdx.x;
    const int brow = blockIdx.y * 128;
    const int bcol = blockIdx.x * 128;
    const int wid  = tid >> 5, lane = tid & 31;
    const int wm   = wid >> 2, wn = wid & 3;

    const int lr = tid >> 2, lc = tid & 3;

    const int a_row = (lane & 7) + ((lane >> 3) & 1) * 8;
    const int a_kc  = lane >> 4;
    const int b_row = (lane & 7) + ((lane >> 4) & 1) * 8;
    const int b_kc  = (lane >> 3) & 1;

    float acc[4][4][4];
#pragma unroll
    for (int i = 0; i < 4; i++)
#pragma unroll
        for (int j = 0; j < 4; j++)
#pragma unroll
            for (int q = 0; q < 4; q++) acc[i][j][q] = 0.0f;

    auto issue_stage = [&](int stage, int k0) {
        uint32_t st = sb + stage * STAGE_BYTES;
#pragma unroll
        for (int p = 0; p < 2; ++p) {
            int r = lr + p * 64;
            uint32_t o = sw_off(r, lc);
            size_t ga = (size_t)(brow + r) * K + k0 + lc * 8;
            size_t gb = (size_t)(bcol + r) * K + k0 + lc * 8;
            cp16(st + OFF_AH + o, Ah + ga);
            cp16(st + OFF_AL + o, Al + ga);
            cp16(st + OFF_BH + o, Bh + gb);
            cp16(st + OFF_BL + o, Bl + gb);
        }
        asm volatile("cp.async.commit_group;");
    };

    const int niter = K / BKQ;
    issue_stage(0, 0);
    if (niter > 1) issue_stage(1, BKQ);

    for (int it = 0; it < niter; ++it) {
        if (it + 1 < niter) asm volatile("cp.async.wait_group 1;");
        else                asm volatile("cp.async.wait_group 0;");
        __syncthreads();
        if (it + 2 < niter) issue_stage((it + 2) % NSTAGE, (it + 2) * BKQ);

        const uint32_t st = sb + (it % NSTAGE) * STAGE_BYTES;

#pragma unroll
        for (int ks = 0; ks < 2; ++ks) {
            uint32_t ah[4][4], al[4][4], bh[4][2], bl[4][2];
#pragma unroll
            for (int pr = 0; pr < 2; ++pr) {
                int row = wn * 32 + pr * 16 + b_row;
                uint32_t ad = st + OFF_BH + sw_off(row, ks * 2 + b_kc);
                ldsm4(bh[2 * pr][0], bh[2 * pr][1],
                      bh[2 * pr + 1][0], bh[2 * pr + 1][1], ad);
            }
#pragma unroll
            for (int mt = 0; mt < 4; ++mt) {
                int row = wm * 64 + mt * 16 + a_row;
                uint32_t ad = st + OFF_AH + sw_off(row, ks * 2 + a_kc);
                ldsm4(ah[mt][0], ah[mt][1], ah[mt][2], ah[mt][3], ad);
            }
#pragma unroll
            for (int mt = 0; mt < 4; ++mt)
#pragma unroll
                for (int nt = 0; nt < 4; ++nt)
                    mma16816(acc[mt][nt], ah[mt], bh[nt]);
#pragma unroll
            for (int mt = 0; mt < 4; ++mt) {
                int row = wm * 64 + mt * 16 + a_row;
                uint32_t ad = st + OFF_AL + sw_off(row, ks * 2 + a_kc);
                ldsm4(al[mt][0], al[mt][1], al[mt][2], al[mt][3], ad);
            }
#pragma unroll
            for (int mt = 0; mt < 4; ++mt)
#pragma unroll
                for (int nt = 0; nt < 4; ++nt)
                    mma16816(acc[mt][nt], al[mt], bh[nt]);
#pragma unroll
            for (int pr = 0; pr < 2; ++pr) {
                int row = wn * 32 + pr * 16 + b_row;
                uint32_t ad = st + OFF_BL + sw_off(row, ks * 2 + b_kc);
                ldsm4(bl[2 * pr][0], bl[2 * pr][1],
                      bl[2 * pr + 1][0], bl[2 * pr + 1][1], ad);
            }
#pragma unroll
            for (int mt = 0; mt < 4; ++mt)
#pragma unroll
                for (int nt = 0; nt < 4; ++nt)
                    mma16816(acc[mt][nt], ah[mt], bl[nt]);
        }
    }

    const int gid = lane >> 2, tig = lane & 3;
#pragma unroll
    for (int mt = 0; mt < 4; ++mt) {
#pragma unroll
        for (int nt = 0; nt < 4; ++nt) {
            int row = brow + wm * 64 + mt * 16 + gid;
            int col = bcol + wn * 32 + nt * 8 + tig * 2;
            float b0 = bias[col], b1 = bias[col + 1];
            float2 v0 = make_float2(acc[mt][nt][0] + b0, acc[mt][nt][1] + b1);
            float2 v1 = make_float2(acc[mt][nt][2] + b0, acc[mt][nt][3] + b1);
            *(float2*)(Cout + (size_t)row * N + col) = v0;
            *(float2*)(Cout + (size_t)(row + 8) * N + col) = v1;
        }
    }
}

// ========================= fp32 -> bf16 hi/lo split =========================
__global__ void split_kernel(const float* __restrict__ in,
                             __nv_bfloat16* __restrict__ h,
                             __nv_bfloat16* __restrict__ l, int n)
{
    int i = blockIdx.x * blockDim.x + threadIdx.x;
    if (i < n) {
        float v = in[i];
        __nv_bfloat16 hh = __float2bfloat16(v);
        h[i] = hh;
        l[i] = __float2bfloat16(v - __bfloat162float(hh));
    }
}

// ============== weight transpose + split: W[K][N] -> Wt[N][K] hi/lo =========
__global__ void wsplit_t_kernel(const float* __restrict__ W,
                                __nv_bfloat16* __restrict__ Wth,
                                __nv_bfloat16* __restrict__ Wtl, int K, int N)
{
    __shared__ float t[32][33];
    const int n0 = blockIdx.x * 32, k0 = blockIdx.y * 32;
    const int tx = threadIdx.x, ty = threadIdx.y;
#pragma unroll
    for (int j = 0; j < 4; ++j)
        t[ty + j * 8][tx] = W[(size_t)(k0 + ty + j * 8) * N + n0 + tx];
    __syncthreads();
#pragma unroll
    for (int j = 0; j < 4; ++j) {
        int nn = ty + j * 8;
        float v = t[tx][nn];
        __nv_bfloat16 hh = __float2bfloat16(v);
        size_t o = (size_t)(n0 + nn) * K + k0 + tx;
        Wth[o] = hh;
        Wtl[o] = __float2bfloat16(v - __bfloat162float(hh));
    }
}

// ============ single-pass top-4 + rowsum (branchless scalar regs) ===========
__device__ __forceinline__ void ins4(float& v0, int& i0, float& v1, int& i1,
                                     float& v2, int& i2, float& v3, int& i3,
                                     float val, int idx)
{
    bool b0 = (val > v0) | ((val == v0) & (idx < i0));
    bool b1 = (val > v1) | ((val == v1) & (idx < i1));
    bool b2 = (val > v2) | ((val == v2) & (idx < i2));
    bool b3 = (val > v3) | ((val == v3) & (idx < i3));
    v3 = b3 ? (b2 ? v2 : val) : v3;  i3 = b3 ? (b2 ? i2 : idx) : i3;
    v2 = b2 ? (b1 ? v1 : val) : v2;  i2 = b2 ? (b1 ? i1 : idx) : i2;
    v1 = b1 ? (b0 ? v0 : val) : v1;  i1 = b1 ? (b0 ? i0 : idx) : i1;
    v0 = b0 ? val : v0;              i0 = b0 ? idx : i0;
}

__global__ void topk_kernel(const float* __restrict__ tau,
                            int* __restrict__ topk,
                            float* __restrict__ rowsum, int T)
{
    const int row  = blockIdx.x;
    const int tid  = threadIdx.x;
    const int lane = tid & 31, wid = tid >> 5;
    const float* tr = tau + (size_t)row * T;

    float v0 = -INFINITY, v1 = -INFINITY, v2 = -INFINITY, v3 = -INFINITY;
    int   i0 = 0x7FFFFFFF, i1 = 0x7FFFFFFF, i2 = 0x7FFFFFFF, i3 = 0x7FFFFFFF;
    float s = 0.0f;

    for (int i = tid; i < T; i += 256) {
        float val = tr[i];
        s += val;
        ins4(v0, i0, v1, i1, v2, i2, v3, i3, val, i);
    }

#pragma unroll
    for (int off = 16; off > 0; off >>= 1) {
        s += __shfl_xor_sync(0xFFFFFFFFu, s, off);
        float w0 = __shfl_xor_sync(0xFFFFFFFFu, v0, off);
        int   j0 = __shfl_xor_sync(0xFFFFFFFFu, i0, off);
        float w1 = __shfl_xor_sync(0xFFFFFFFFu, v1, off);
        int   j1 = __shfl_xor_sync(0xFFFFFFFFu, i1, off);
        float w2 = __shfl_xor_sync(0xFFFFFFFFu, v2, off);
        int   j2 = __shfl_xor_sync(0xFFFFFFFFu, i2, off);
        float w3 = __shfl_xor_sync(0xFFFFFFFFu, v3, off);
        int   j3 = __shfl_xor_sync(0xFFFFFFFFu, i3, off);
        ins4(v0, i0, v1, i1, v2, i2, v3, i3, w0, j0);
        ins4(v0, i0, v1, i1, v2, i2, v3, i3, w1, j1);
        ins4(v0, i0, v1, i1, v2, i2, v3, i3, w2, j2);
        ins4(v0, i0, v1, i1, v2, i2, v3, i3, w3, j3);
    }

    __shared__ float wv[8][4];
    __shared__ int   wi[8][4];
    __shared__ float ws[8];
    if (lane == 0) {
        wv[wid][0] = v0; wv[wid][1] = v1; wv[wid][2] = v2; wv[wid][3] = v3;
        wi[wid][0] = i0; wi[wid][1] = i1; wi[wid][2] = i2; wi[wid][3] = i3;
        ws[wid] = s;
    }
    __syncthreads();

    if (tid == 0) {
        float sum = ws[0];
#pragma unroll
        for (int w = 1; w < 8; ++w) {
            sum += ws[w];
            ins4(v0, i0, v1, i1, v2, i2, v3, i3, wv[w][0], wi[w][0]);
            ins4(v0, i0, v1, i1, v2, i2, v3, i3, wv[w][1], wi[w][1]);
            ins4(v0, i0, v1, i1, v2, i2, v3, i3, wv[w][2], wi[w][2]);
            ins4(v0, i0, v1, i1, v2, i2, v3, i3, wv[w][3], wi[w][3]);
        }
        rowsum[row] = sum;
        int4 r = make_int4(i0, i1, i2, i3);
        *(int4*)(topk + row * TOPK) = r;
    }
}

// ================= sparse attention core (float2 vectorized) ================
// lane l handles dims 2l, 2l+1 of its head (64 dims / 32 lanes).
__global__ void attn_kernel(const float* __restrict__ qkv,
                            const float* __restrict__ tau,
                            const int* __restrict__ topk,
                            __nv_bfloat16* __restrict__ aoh,
                            __nv_bfloat16* __restrict__ aol,
                            float* __restrict__ sig3,
                            float* __restrict__ sigsum,
                            int T, int C)
{
    const int row = blockIdx.x;
    const int b   = row / T;
    const int h   = threadIdx.x >> 5;
    const int l   = threadIdx.x & 31;
    const int C3  = 3 * C;

    __shared__ int   sidx[TOPK];
    __shared__ float sbias[TOPK];
    __shared__ float satt[NUM_HEADS][TOPK];

    if (threadIdx.x < TOPK) {
        int id = topk[row * TOPK + threadIdx.x];
        sidx[threadIdx.x]  = id;
        sbias[threadIdx.x] = GAMMA * logf(tau[(size_t)row * T + id] + 1e-8f);
    }
    __syncthreads();

    const float* qrow = qkv + (size_t)row * C3 + h * 64;
    const float2 q01 = *(const float2*)(qrow + 2 * l);

    float logit[TOPK];
#pragma unroll
    for (int j = 0; j < TOPK; j++) {
        const float* krow = qkv + (size_t)(b * T + sidx[j]) * C3 + C + h * 64;
        float2 kk = *(const float2*)(krow + 2 * l);
        float p = q01.x * kk.x + q01.y * kk.y;
#pragma unroll
        for (int off = 16; off > 0; off >>= 1)
            p += __shfl_xor_sync(0xFFFFFFFFu, p, off);
        logit[j] = p * 0.125f + sbias[j];
    }

    float m = fmaxf(fmaxf(logit[0], logit[1]), fmaxf(logit[2], logit[3]));
    float e[TOPK], den = 0.0f;
#pragma unroll
    for (int j = 0; j < TOPK; j++) { e[j] = expf(logit[j] - m); den += e[j]; }
    float inv = 1.0f / den;
    float a[TOPK];
#pragma unroll
    for (int j = 0; j < TOPK; j++) a[j] = e[j] * inv;

    float o0 = 0.0f, o1 = 0.0f;
#pragma unroll
    for (int j = 0; j < TOPK; j++) {
        const float* vrow = qkv + (size_t)(b * T + sidx[j]) * C3 + 2 * C + h * 64;
        float2 vv = *(const float2*)(vrow + 2 * l);
        o0 = fmaf(a[j], vv.x, o0);
        o1 = fmaf(a[j], vv.y, o1);
    }
    {
        size_t base = (size_t)row * C + h * 64 + 2 * l;
        __nv_bfloat16 h0 = __float2bfloat16(o0);
        __nv_bfloat16 h1 = __float2bfloat16(o1);
        __nv_bfloat162 hv; hv.x = h0; hv.y = h1;
        *(__nv_bfloat162*)(aoh + base) = hv;
        __nv_bfloat162 lv;
        lv.x = __float2bfloat16(o0 - __bfloat162float(h0));
        lv.y = __float2bfloat16(o1 - __bfloat162float(h1));
        *(__nv_bfloat162*)(aol + base) = lv;
    }

    if (l == 0) {
#pragma unroll
        for (int j = 0; j < TOPK; j++) satt[h][j] = a[j];
    }
    __syncthreads();

    if (threadIdx.x == 0) {
        float ss = 0.0f;
#pragma unroll
        for (int j = 0; j < TOPK; j++) {
            float sgn = 0.0f;
#pragma unroll
            for (int hh = 0; hh < NUM_HEADS; hh++) sgn += satt[hh][j];
            sgn *= (1.0f / NUM_HEADS);
            float s3 = sgn * sgn * sgn;
            sig3[row * TOPK + j] = s3;
            ss += s3;
        }
        sigsum[row] = ss;
    }
}

// ============== tau EMA: fused branchless stream + in-block fixup ===========
__global__ void tau_kernel(const float* __restrict__ tau,
                           const int* __restrict__ topk,
                           const float* __restrict__ sig3,
                           const float* __restrict__ rowsum,
                           const float* __restrict__ sigsum,
                           float* __restrict__ tau_out, int T)
{
    const int row = blockIdx.x;
    const float keep = 1.0f - RHO;
    const float denom = keep * rowsum[row] + sigsum[row] + 1e-8f;
    const float ki  = keep / denom;
    const float inv = 1.0f / denom;

    const float4* tr = (const float4*)(tau + (size_t)row * T);
    float4* to = (float4*)(tau_out + (size_t)row * T);
    const int n4 = T >> 2;
    for (int i = threadIdx.x; i < n4; i += blockDim.x) {
        float4 v = tr[i];
        v.x = fminf(v.x * ki, TAU_CLIP);
        v.y = fminf(v.y * ki, TAU_CLIP);
        v.z = fminf(v.z * ki, TAU_CLIP);
        v.w = fminf(v.w * ki, TAU_CLIP);
        to[i] = v;
    }
    __syncthreads();

    if (threadIdx.x < TOPK) {
        int s = topk[row * TOPK + threadIdx.x];
        float v = keep * tau[(size_t)row * T + s] + sig3[row * TOPK + threadIdx.x];
        tau_out[(size_t)row * T + s] = fminf(v * inv, TAU_CLIP);
    }
}

// ========================= launch ===========================================
extern "C" void kernel_launch(void* const* d_in, const int* in_sizes, int n_in,
                              void* d_out, int out_size)
{
    const float* x     = (const float*)d_in[0];
    const float* tau   = (const float*)d_in[1];
    const float* Wqkv  = (const float*)d_in[2];
    const float* bqkv  = (const float*)d_in[3];
    const float* Wproj = (const float*)d_in[4];
    const float* bproj = (const float*)d_in[5];

    const int C  = in_sizes[5];                 // 512
    const int BT = in_sizes[0] / C;             // 4096
    const int T  = in_sizes[1] / BT;            // 2048
    const int C3 = 3 * C;

    float* out_main = (float*)d_out;
    float* tau_out  = out_main + (size_t)BT * C;

    float* qkv;            cudaGetSymbolAddress((void**)&qkv,  g_qkv);
    __nv_bfloat16 *xh, *xl, *aoh, *aol, *wqh, *wql, *wph, *wpl;
    cudaGetSymbolAddress((void**)&xh,  g_xh);
    cudaGetSymbolAddress((void**)&xl,  g_xl);
    cudaGetSymbolAddress((void**)&aoh, g_aoh);
    cudaGetSymbolAddress((void**)&aol, g_aol);
    cudaGetSymbolAddress((void**)&wqh, g_wqh);
    cudaGetSymbolAddress((void**)&wql, g_wql);
    cudaGetSymbolAddress((void**)&wph, g_wph);
    cudaGetSymbolAddress((void**)&wpl, g_wpl);
    int*   topk;   cudaGetSymbolAddress((void**)&topk,   g_topk);
    float* sig3;   cudaGetSymbolAddress((void**)&sig3,   g_sig3);
    float* rowsum; cudaGetSymbolAddress((void**)&rowsum, g_rowsum);
    float* sigsum; cudaGetSymbolAddress((void**)&sigsum, g_sigsum);

    // one-time setup: smem attribute + side stream + fork/join events
    static cudaStream_t s1 = nullptr;
    static cudaEvent_t evFork = nullptr, evSide = nullptr,
                       evAttn = nullptr, evTau = nullptr;
    if (s1 == nullptr) {
        cudaFuncSetAttribute(gemm_bf16x3_kernel,
                             cudaFuncAttributeMaxDynamicSharedMemorySize,
                             GEMM_SMEM);
        cudaStreamCreateWithFlags(&s1, cudaStreamNonBlocking);
        cudaEventCreateWithFlags(&evFork, cudaEventDisableTiming);
        cudaEventCreateWithFlags(&evSide, cudaEventDisableTiming);
        cudaEventCreateWithFlags(&evAttn, cudaEventDisableTiming);
        cudaEventCreateWithFlags(&evTau,  cudaEventDisableTiming);
    }

    // ---- fork: side stream runs topk + Wproj split, overlapping qkv GEMM ----
    cudaEventRecord(evFork, 0);
    cudaStreamWaitEvent(s1, evFork, 0);
    topk_kernel<<<BT, 256, 0, s1>>>(tau, topk, rowsum, T);
    {
        dim3 tb(32, 8);
        wsplit_t_kernel<<<dim3(C / 32, C / 32), tb, 0, s1>>>(Wproj, wph, wpl, C, C);
    }
    cudaEventRecord(evSide, s1);

    // ---- main stream: operand prep + qkv GEMM ----
    {
        int n = BT * C;
        split_kernel<<<(n + 255) / 256, 256>>>(x, xh, xl, n);
        dim3 tb(32, 8);
        wsplit_t_kernel<<<dim3(C3 / 32, C / 32), tb>>>(Wqkv, wqh, wql, C, C3);
    }
    {
        dim3 grid(C3 / 128, BT / 128);
        gemm_bf16x3_kernel<<<grid, 256, GEMM_SMEM>>>(xh, xl, wqh, wql,
                                                     bqkv, qkv, BT, C3, C);
    }

    // ---- join: attention needs qkv (main) + topk (side) ----
    cudaStreamWaitEvent(0, evSide, 0);
    attn_kernel<<<BT, 256>>>(qkv, tau, topk, aoh, aol, sig3, sigsum, T, C);
    cudaEventRecord(evAttn, 0);

    // ---- fork again: tau update (DRAM-bound) overlaps proj GEMM (tensor) ----
    cudaStreamWaitEvent(s1, evAttn, 0);
    tau_kernel<<<BT, 256, 0, s1>>>(tau, topk, sig3, rowsum, sigsum, tau_out, T);
    cudaEventRecord(evTau, s1);

    // ---- main stream: proj GEMM ----
    {
        dim3 grid(C / 128, BT / 128);
        gemm_bf16x3_kernel<<<grid, 256, GEMM_SMEM>>>(aoh, aol, wph, wpl,
                                                     bproj, out_main, BT, C, C);
    }
    // ---- final join so all captured work ends on the origin stream ----
    cudaStreamWaitEvent(0, evTau, 0);
}

// round 15
// speedup vs baseline: 1.1719x; 1.1086x over previous
#include <cuda_runtime.h>
#include <cuda_bf16.h>
#include <cuda_fp16.h>
#include <math.h>
#include <stdint.h>

// Problem constants: B=2, T=2048, C=512, H=8, D=64, K=4
#define GAMMA 2.5f
#define TOPK 4
#define RHO 0.085f
#define TAU_CLIP 5.0f
#define NUM_HEADS 8

#define MAX_BT   4096
#define MAX_C    512
#define MAX_3C   1536

// ------------------------- scratch (device globals) -------------------------
__device__ float   g_qkv[MAX_BT * MAX_3C];
__device__ __half  g_xh[MAX_BT * MAX_C];      // x split hi
__device__ __half  g_xl[MAX_BT * MAX_C];      // x split lo
__device__ __half  g_aoh[MAX_BT * MAX_C];     // attn out split hi
__device__ __half  g_aol[MAX_BT * MAX_C];     // attn out split lo
__device__ __half  g_wqh[MAX_3C * MAX_C];     // Wqkv^T fp16 [N][K]
__device__ __half  g_wph[MAX_C * MAX_C];      // Wproj^T fp16 [N][K]
__device__ int   g_topk[MAX_BT * TOPK];
__device__ float g_sig3[MAX_BT * TOPK];
__device__ float g_rowsum[MAX_BT];
__device__ float g_sigsum[MAX_BT];

// ========================= helpers ==========================================
__device__ __forceinline__ uint32_t smem_u32(const void* p) {
    uint32_t a;
    asm("{ .reg .u64 t; cvta.to.shared.u64 t, %1; cvt.u32.u64 %0, t; }"
        : "=r"(a) : "l"(p));
    return a;
}

__device__ __forceinline__ void ldsm4(uint32_t& r0, uint32_t& r1,
                                      uint32_t& r2, uint32_t& r3, uint32_t a) {
    asm volatile("ldmatrix.sync.aligned.m8n8.x4.shared.b16 {%0,%1,%2,%3}, [%4];"
                 : "=r"(r0), "=r"(r1), "=r"(r2), "=r"(r3) : "r"(a));
}

__device__ __forceinline__ void mma16816f16(float* d, const uint32_t* a,
                                            const uint32_t* b) {
    asm volatile(
        "mma.sync.aligned.m16n8k16.row.col.f32.f16.f16.f32 "
        "{%0,%1,%2,%3},{%4,%5,%6,%7},{%8,%9},{%0,%1,%2,%3};"
        : "+f"(d[0]), "+f"(d[1]), "+f"(d[2]), "+f"(d[3])
        : "r"(a[0]), "r"(a[1]), "r"(a[2]), "r"(a[3]), "r"(b[0]), "r"(b[1]));
}

__device__ __forceinline__ void cp16(uint32_t dst, const void* src) {
    asm volatile("cp.async.cg.shared.global [%0], [%1], 16;"
                 :: "r"(dst), "l"(src));
}

__device__ __forceinline__ uint32_t sw_off(int row, int kc) {
    return (uint32_t)(row * 64 + ((kc ^ ((row >> 1) & 3)) << 4));
}

// ========================= fp16x2 HMMA GEMM =================================
// D = (Ah+Al) @ Bh^T + bias. A split into fp16 hi/lo; B plain fp16 (rel err
// 2^-12, within 1e-3 budget). 2 MMA passes (hh, lh) instead of bf16x3's 3.
// Tile 128x128x32, 8 warps (warp tile 64x32), 3-stage cp.async pipeline.
#define BKQ 32
#define NSTAGE 3
#define STAGE_BYTES 24576
#define OFF_AH 0
#define OFF_AL 8192
#define OFF_BH 16384
#define GEMM_SMEM (NSTAGE * STAGE_BYTES)

__global__ __launch_bounds__(256, 2) void gemm_fp16x2_kernel(
    const __half* __restrict__ Ah, const __half* __restrict__ Al,
    const __half* __restrict__ Bh,
    const float* __restrict__ bias, float* __restrict__ Cout,
    int M, int N, int K)
{
    extern __shared__ char smem[];
    const uint32_t sb = smem_u32(smem);
    const int tid  = threadIdx.x;
    const int brow = blockIdx.y * 128;
    const int bcol = blockIdx.x * 128;
    const int wid  = tid >> 5, lane = tid & 31;
    const int wm   = wid >> 2, wn = wid & 3;

    const int lr = tid >> 2, lc = tid & 3;

    const int a_row = (lane & 7) + ((lane >> 3) & 1) * 8;
    const int a_kc  = lane >> 4;
    const int b_row = (lane & 7) + ((lane >> 4) & 1) * 8;
    const int b_kc  = (lane >> 3) & 1;

    float acc[4][4][4];
#pragma unroll
    for (int i = 0; i < 4; i++)
#pragma unroll
        for (int j = 0; j < 4; j++)
#pragma unroll
            for (int q = 0; q < 4; q++) acc[i][j][q] = 0.0f;

    auto issue_stage = [&](int stage, int k0) {
        uint32_t st = sb + stage * STAGE_BYTES;
#pragma unroll
        for (int p = 0; p < 2; ++p) {
            int r = lr + p * 64;
            uint32_t o = sw_off(r, lc);
            size_t ga = (size_t)(brow + r) * K + k0 + lc * 8;
            size_t gb = (size_t)(bcol + r) * K + k0 + lc * 8;
            cp16(st + OFF_AH + o, Ah + ga);
            cp16(st + OFF_AL + o, Al + ga);
            cp16(st + OFF_BH + o, Bh + gb);
        }
        asm volatile("cp.async.commit_group;");
    };

    const int niter = K / BKQ;
    issue_stage(0, 0);
    if (niter > 1) issue_stage(1, BKQ);

    for (int it = 0; it < niter; ++it) {
        if (it + 1 < niter) asm volatile("cp.async.wait_group 1;");
        else                asm volatile("cp.async.wait_group 0;");
        __syncthreads();
        if (it + 2 < niter) issue_stage((it + 2) % NSTAGE, (it + 2) * BKQ);

        const uint32_t st = sb + (it % NSTAGE) * STAGE_BYTES;

#pragma unroll
        for (int ks = 0; ks < 2; ++ks) {
            uint32_t ah[4][4], al[4][4], bh[4][2];
#pragma unroll
            for (int pr = 0; pr < 2; ++pr) {
                int row = wn * 32 + pr * 16 + b_row;
                uint32_t ad = st + OFF_BH + sw_off(row, ks * 2 + b_kc);
                ldsm4(bh[2 * pr][0], bh[2 * pr][1],
                      bh[2 * pr + 1][0], bh[2 * pr + 1][1], ad);
            }
#pragma unroll
            for (int mt = 0; mt < 4; ++mt) {
                int row = wm * 64 + mt * 16 + a_row;
                uint32_t ad = st + OFF_AH + sw_off(row, ks * 2 + a_kc);
                ldsm4(ah[mt][0], ah[mt][1], ah[mt][2], ah[mt][3], ad);
            }
#pragma unroll
            for (int mt = 0; mt < 4; ++mt)
#pragma unroll
                for (int nt = 0; nt < 4; ++nt)
                    mma16816f16(acc[mt][nt], ah[mt], bh[nt]);
#pragma unroll
            for (int mt = 0; mt < 4; ++mt) {
                int row = wm * 64 + mt * 16 + a_row;
                uint32_t ad = st + OFF_AL + sw_off(row, ks * 2 + a_kc);
                ldsm4(al[mt][0], al[mt][1], al[mt][2], al[mt][3], ad);
            }
#pragma unroll
            for (int mt = 0; mt < 4; ++mt)
#pragma unroll
                for (int nt = 0; nt < 4; ++nt)
                    mma16816f16(acc[mt][nt], al[mt], bh[nt]);
        }
    }

    const int gid = lane >> 2, tig = lane & 3;
#pragma unroll
    for (int mt = 0; mt < 4; ++mt) {
#pragma unroll
        for (int nt = 0; nt < 4; ++nt) {
            int row = brow + wm * 64 + mt * 16 + gid;
            int col = bcol + wn * 32 + nt * 8 + tig * 2;
            float b0 = bias[col], b1 = bias[col + 1];
            float2 v0 = make_float2(acc[mt][nt][0] + b0, acc[mt][nt][1] + b1);
            float2 v1 = make_float2(acc[mt][nt][2] + b0, acc[mt][nt][3] + b1);
            *(float2*)(Cout + (size_t)row * N + col) = v0;
            *(float2*)(Cout + (size_t)(row + 8) * N + col) = v1;
        }
    }
}

// ========================= fp32 -> fp16 hi/lo split =========================
__global__ void split_kernel(const float* __restrict__ in,
                             __half* __restrict__ h,
                             __half* __restrict__ l, int n)
{
    int i = blockIdx.x * blockDim.x + threadIdx.x;
    if (i < n) {
        float v = in[i];
        __half hh = __float2half(v);
        h[i] = hh;
        l[i] = __float2half(v - __half2float(hh));
    }
}

// ============ weight transpose to fp16: W[K][N] -> Wt[N][K] =================
__global__ void wsplit_t_kernel(const float* __restrict__ W,
                                __half* __restrict__ Wth, int K, int N)
{
    __shared__ float t[32][33];
    const int n0 = blockIdx.x * 32, k0 = blockIdx.y * 32;
    const int tx = threadIdx.x, ty = threadIdx.y;
#pragma unroll
    for (int j = 0; j < 4; ++j)
        t[ty + j * 8][tx] = W[(size_t)(k0 + ty + j * 8) * N + n0 + tx];
    __syncthreads();
#pragma unroll
    for (int j = 0; j < 4; ++j) {
        int nn = ty + j * 8;
        Wth[(size_t)(n0 + nn) * K + k0 + tx] = __float2half(t[tx][nn]);
    }
}

// ============ single-pass top-4 + rowsum (branchless scalar regs) ===========
__device__ __forceinline__ void ins4(float& v0, int& i0, float& v1, int& i1,
                                     float& v2, int& i2, float& v3, int& i3,
                                     float val, int idx)
{
    bool b0 = (val > v0) | ((val == v0) & (idx < i0));
    bool b1 = (val > v1) | ((val == v1) & (idx < i1));
    bool b2 = (val > v2) | ((val == v2) & (idx < i2));
    bool b3 = (val > v3) | ((val == v3) & (idx < i3));
    v3 = b3 ? (b2 ? v2 : val) : v3;  i3 = b3 ? (b2 ? i2 : idx) : i3;
    v2 = b2 ? (b1 ? v1 : val) : v2;  i2 = b2 ? (b1 ? i1 : idx) : i2;
    v1 = b1 ? (b0 ? v0 : val) : v1;  i1 = b1 ? (b0 ? i0 : idx) : i1;
    v0 = b0 ? val : v0;              i0 = b0 ? idx : i0;
}

__global__ void topk_kernel(const float* __restrict__ tau,
                            int* __restrict__ topk,
                            float* __restrict__ rowsum, int T)
{
    const int row  = blockIdx.x;
    const int tid  = threadIdx.x;
    const int lane = tid & 31, wid = tid >> 5;
    const float* tr = tau + (size_t)row * T;

    float v0 = -INFINITY, v1 = -INFINITY, v2 = -INFINITY, v3 = -INFINITY;
    int   i0 = 0x7FFFFFFF, i1 = 0x7FFFFFFF, i2 = 0x7FFFFFFF, i3 = 0x7FFFFFFF;
    float s = 0.0f;

    for (int i = tid; i < T; i += 256) {
        float val = tr[i];
        s += val;
        ins4(v0, i0, v1, i1, v2, i2, v3, i3, val, i);
    }

#pragma unroll
    for (int off = 16; off > 0; off >>= 1) {
        s += __shfl_xor_sync(0xFFFFFFFFu, s, off);
        float w0 = __shfl_xor_sync(0xFFFFFFFFu, v0, off);
        int   j0 = __shfl_xor_sync(0xFFFFFFFFu, i0, off);
        float w1 = __shfl_xor_sync(0xFFFFFFFFu, v1, off);
        int   j1 = __shfl_xor_sync(0xFFFFFFFFu, i1, off);
        float w2 = __shfl_xor_sync(0xFFFFFFFFu, v2, off);
        int   j2 = __shfl_xor_sync(0xFFFFFFFFu, i2, off);
        float w3 = __shfl_xor_sync(0xFFFFFFFFu, v3, off);
        int   j3 = __shfl_xor_sync(0xFFFFFFFFu, i3, off);
        ins4(v0, i0, v1, i1, v2, i2, v3, i3, w0, j0);
        ins4(v0, i0, v1, i1, v2, i2, v3, i3, w1, j1);
        ins4(v0, i0, v1, i1, v2, i2, v3, i3, w2, j2);
        ins4(v0, i0, v1, i1, v2, i2, v3, i3, w3, j3);
    }

    __shared__ float wv[8][4];
    __shared__ int   wi[8][4];
    __shared__ float ws[8];
    if (lane == 0) {
        wv[wid][0] = v0; wv[wid][1] = v1; wv[wid][2] = v2; wv[wid][3] = v3;
        wi[wid][0] = i0; wi[wid][1] = i1; wi[wid][2] = i2; wi[wid][3] = i3;
        ws[wid] = s;
    }
    __syncthreads();

    if (tid == 0) {
        float sum = ws[0];
#pragma unroll
        for (int w = 1; w < 8; ++w) {
            sum += ws[w];
            ins4(v0, i0, v1, i1, v2, i2, v3, i3, wv[w][0], wi[w][0]);
            ins4(v0, i0, v1, i1, v2, i2, v3, i3, wv[w][1], wi[w][1]);
            ins4(v0, i0, v1, i1, v2, i2, v3, i3, wv[w][2], wi[w][2]);
            ins4(v0, i0, v1, i1, v2, i2, v3, i3, wv[w][3], wi[w][3]);
        }
        rowsum[row] = sum;
        int4 r = make_int4(i0, i1, i2, i3);
        *(int4*)(topk + row * TOPK) = r;
    }
}

// ================= sparse attention core (float2 vectorized) ================
__global__ void attn_kernel(const float* __restrict__ qkv,
                            const float* __restrict__ tau,
                            const int* __restrict__ topk,
                            __half* __restrict__ aoh,
                            __half* __restrict__ aol,
                            float* __restrict__ sig3,
                            float* __restrict__ sigsum,
                            int T, int C)
{
    const int row = blockIdx.x;
    const int b   = row / T;
    const int h   = threadIdx.x >> 5;
    const int l   = threadIdx.x & 31;
    const int C3  = 3 * C;

    __shared__ int   sidx[TOPK];
    __shared__ float sbias[TOPK];
    __shared__ float satt[NUM_HEADS][TOPK];

    if (threadIdx.x < TOPK) {
        int id = topk[row * TOPK + threadIdx.x];
        sidx[threadIdx.x]  = id;
        sbias[threadIdx.x] = GAMMA * logf(tau[(size_t)row * T + id] + 1e-8f);
    }
    __syncthreads();

    const float* qrow = qkv + (size_t)row * C3 + h * 64;
    const float2 q01 = *(const float2*)(qrow + 2 * l);

    float logit[TOPK];
#pragma unroll
    for (int j = 0; j < TOPK; j++) {
        const float* krow = qkv + (size_t)(b * T + sidx[j]) * C3 + C + h * 64;
        float2 kk = *(const float2*)(krow + 2 * l);
        float p = q01.x * kk.x + q01.y * kk.y;
#pragma unroll
        for (int off = 16; off > 0; off >>= 1)
            p += __shfl_xor_sync(0xFFFFFFFFu, p, off);
        logit[j] = p * 0.125f + sbias[j];
    }

    float m = fmaxf(fmaxf(logit[0], logit[1]), fmaxf(logit[2], logit[3]));
    float e[TOPK], den = 0.0f;
#pragma unroll
    for (int j = 0; j < TOPK; j++) { e[j] = expf(logit[j] - m); den += e[j]; }
    float inv = 1.0f / den;
    float a[TOPK];
#pragma unroll
    for (int j = 0; j < TOPK; j++) a[j] = e[j] * inv;

    float o0 = 0.0f, o1 = 0.0f;
#pragma unroll
    for (int j = 0; j < TOPK; j++) {
        const float* vrow = qkv + (size_t)(b * T + sidx[j]) * C3 + 2 * C + h * 64;
        float2 vv = *(const float2*)(vrow + 2 * l);
        o0 = fmaf(a[j], vv.x, o0);
        o1 = fmaf(a[j], vv.y, o1);
    }
    {
        size_t base = (size_t)row * C + h * 64 + 2 * l;
        __half h0 = __float2half(o0);
        __half h1 = __float2half(o1);
        __half2 hv; hv.x = h0; hv.y = h1;
        *(__half2*)(aoh + base) = hv;
        __half2 lv;
        lv.x = __float2half(o0 - __half2float(h0));
        lv.y = __float2half(o1 - __half2float(h1));
        *(__half2*)(aol + base) = lv;
    }

    if (l == 0) {
#pragma unroll
        for (int j = 0; j < TOPK; j++) satt[h][j] = a[j];
    }
    __syncthreads();

    if (threadIdx.x == 0) {
        float ss = 0.0f;
#pragma unroll
        for (int j = 0; j < TOPK; j++) {
            float sgn = 0.0f;
#pragma unroll
            for (int hh = 0; hh < NUM_HEADS; hh++) sgn += satt[hh][j];
            sgn *= (1.0f / NUM_HEADS);
            float s3 = sgn * sgn * sgn;
            sig3[row * TOPK + j] = s3;
            ss += s3;
        }
        sigsum[row] = ss;
    }
}

// ============== tau EMA: fused branchless stream + in-block fixup ===========
__global__ void tau_kernel(const float* __restrict__ tau,
                           const int* __restrict__ topk,
                           const float* __restrict__ sig3,
                           const float* __restrict__ rowsum,
                           const float* __restrict__ sigsum,
                           float* __restrict__ tau_out, int T)
{
    const int row = blockIdx.x;
    const float keep = 1.0f - RHO;
    const float denom = keep * rowsum[row] + sigsum[row] + 1e-8f;
    const float ki  = keep / denom;
    const float inv = 1.0f / denom;

    const float4* tr = (const float4*)(tau + (size_t)row * T);
    float4* to = (float4*)(tau_out + (size_t)row * T);
    const int n4 = T >> 2;
    for (int i = threadIdx.x; i < n4; i += blockDim.x) {
        float4 v = tr[i];
        v.x = fminf(v.x * ki, TAU_CLIP);
        v.y = fminf(v.y * ki, TAU_CLIP);
        v.z = fminf(v.z * ki, TAU_CLIP);
        v.w = fminf(v.w * ki, TAU_CLIP);
        to[i] = v;
    }
    __syncthreads();

    if (threadIdx.x < TOPK) {
        int s = topk[row * TOPK + threadIdx.x];
        float v = keep * tau[(size_t)row * T + s] + sig3[row * TOPK + threadIdx.x];
        tau_out[(size_t)row * T + s] = fminf(v * inv, TAU_CLIP);
    }
}

// ========================= launch ===========================================
extern "C" void kernel_launch(void* const* d_in, const int* in_sizes, int n_in,
                              void* d_out, int out_size)
{
    const float* x     = (const float*)d_in[0];
    const float* tau   = (const float*)d_in[1];
    const float* Wqkv  = (const float*)d_in[2];
    const float* bqkv  = (const float*)d_in[3];
    const float* Wproj = (const float*)d_in[4];
    const float* bproj = (const float*)d_in[5];

    const int C  = in_sizes[5];                 // 512
    const int BT = in_sizes[0] / C;             // 4096
    const int T  = in_sizes[1] / BT;            // 2048
    const int C3 = 3 * C;

    float* out_main = (float*)d_out;
    float* tau_out  = out_main + (size_t)BT * C;

    float* qkv;    cudaGetSymbolAddress((void**)&qkv,  g_qkv);
    __half *xh, *xl, *aoh, *aol, *wqh, *wph;
    cudaGetSymbolAddress((void**)&xh,  g_xh);
    cudaGetSymbolAddress((void**)&xl,  g_xl);
    cudaGetSymbolAddress((void**)&aoh, g_aoh);
    cudaGetSymbolAddress((void**)&aol, g_aol);
    cudaGetSymbolAddress((void**)&wqh, g_wqh);
    cudaGetSymbolAddress((void**)&wph, g_wph);
    int*   topk;   cudaGetSymbolAddress((void**)&topk,   g_topk);
    float* sig3;   cudaGetSymbolAddress((void**)&sig3,   g_sig3);
    float* rowsum; cudaGetSymbolAddress((void**)&rowsum, g_rowsum);
    float* sigsum; cudaGetSymbolAddress((void**)&sigsum, g_sigsum);

    // one-time setup: smem attribute + side stream + fork/join events
    static cudaStream_t s1 = nullptr;
    static cudaEvent_t evFork = nullptr, evSide = nullptr,
                       evAttn = nullptr, evTau = nullptr;
    if (s1 == nullptr) {
        cudaFuncSetAttribute(gemm_fp16x2_kernel,
                             cudaFuncAttributeMaxDynamicSharedMemorySize,
                             GEMM_SMEM);
        cudaStreamCreateWithFlags(&s1, cudaStreamNonBlocking);
        cudaEventCreateWithFlags(&evFork, cudaEventDisableTiming);
        cudaEventCreateWithFlags(&evSide, cudaEventDisableTiming);
        cudaEventCreateWithFlags(&evAttn, cudaEventDisableTiming);
        cudaEventCreateWithFlags(&evTau,  cudaEventDisableTiming);
    }

    // ---- fork: side stream runs topk + Wproj prep, overlapping qkv GEMM ----
    cudaEventRecord(evFork, 0);
    cudaStreamWaitEvent(s1, evFork, 0);
    topk_kernel<<<BT, 256, 0, s1>>>(tau, topk, rowsum, T);
    {
        dim3 tb(32, 8);
        wsplit_t_kernel<<<dim3(C / 32, C / 32), tb, 0, s1>>>(Wproj, wph, C, C);
    }
    cudaEventRecord(evSide, s1);

    // ---- main stream: operand prep + qkv GEMM ----
    {
        int n = BT * C;
        split_kernel<<<(n + 255) / 256, 256>>>(x, xh, xl, n);
        dim3 tb(32, 8);
        wsplit_t_kernel<<<dim3(C3 / 32, C / 32), tb>>>(Wqkv, wqh, C, C3);
    }
    {
        dim3 grid(C3 / 128, BT / 128);
        gemm_fp16x2_kernel<<<grid, 256, GEMM_SMEM>>>(xh, xl, wqh,
                                                     bqkv, qkv, BT, C3, C);
    }

    // ---- join: attention needs qkv (main) + topk (side) ----
    cudaStreamWaitEvent(0, evSide, 0);
    attn_kernel<<<BT, 256>>>(qkv, tau, topk, aoh, aol, sig3, sigsum, T, C);
    cudaEventRecord(evAttn, 0);

    // ---- fork again: tau update (DRAM-bound) overlaps proj GEMM (tensor) ----
    cudaStreamWaitEvent(s1, evAttn, 0);
    tau_kernel<<<BT, 256, 0, s1>>>(tau, topk, sig3, rowsum, sigsum, tau_out, T);
    cudaEventRecord(evTau, s1);

    // ---- main stream: proj GEMM ----
    {
        dim3 grid(C / 128, BT / 128);
        gemm_fp16x2_kernel<<<grid, 256, GEMM_SMEM>>>(aoh, aol, wph,
                                                     bproj, out_main, BT, C, C);
    }
    // ---- final join so all captured work ends on the origin stream ----
    cudaStreamWaitEvent(0, evTau, 0);
}

// round 16
// speedup vs baseline: 1.2093x; 1.0319x over previous
#include <cuda_runtime.h>
#include <cuda_bf16.h>
#include <cuda_fp16.h>
#include <math.h>
#include <stdint.h>

// Problem constants: B=2, T=2048, C=512, H=8, D=64, K=4
#define GAMMA 2.5f
#define TOPK 4
#define RHO 0.085f
#define TAU_CLIP 5.0f
#define NUM_HEADS 8

#define MAX_BT   4096
#define MAX_C    512
#define MAX_3C   1536

// ------------------------- scratch (device globals) -------------------------
__device__ float   g_qkv[MAX_BT * MAX_3C];
__device__ __half  g_xh[MAX_BT * MAX_C];
__device__ __half  g_xl[MAX_BT * MAX_C];
__device__ __half  g_aoh[MAX_BT * MAX_C];
__device__ __half  g_aol[MAX_BT * MAX_C];
__device__ __half  g_wqh[MAX_3C * MAX_C];
__device__ __half  g_wph[MAX_C * MAX_C];
__device__ int   g_topk[MAX_BT * TOPK];
__device__ float g_sig3[MAX_BT * TOPK];
__device__ float g_rowsum[MAX_BT];
__device__ float g_sigsum[MAX_BT];

// ========================= helpers ==========================================
__device__ __forceinline__ uint32_t smem_u32(const void* p) {
    uint32_t a;
    asm("{ .reg .u64 t; cvta.to.shared.u64 t, %1; cvt.u32.u64 %0, t; }"
        : "=r"(a) : "l"(p));
    return a;
}

__device__ __forceinline__ void ldsm4(uint32_t& r0, uint32_t& r1,
                                      uint32_t& r2, uint32_t& r3, uint32_t a) {
    asm volatile("ldmatrix.sync.aligned.m8n8.x4.shared.b16 {%0,%1,%2,%3}, [%4];"
                 : "=r"(r0), "=r"(r1), "=r"(r2), "=r"(r3) : "r"(a));
}

__device__ __forceinline__ void mma16816f16(float* d, const uint32_t* a,
                                            const uint32_t* b) {
    asm volatile(
        "mma.sync.aligned.m16n8k16.row.col.f32.f16.f16.f32 "
        "{%0,%1,%2,%3},{%4,%5,%6,%7},{%8,%9},{%0,%1,%2,%3};"
        : "+f"(d[0]), "+f"(d[1]), "+f"(d[2]), "+f"(d[3])
        : "r"(a[0]), "r"(a[1]), "r"(a[2]), "r"(a[3]), "r"(b[0]), "r"(b[1]));
}

__device__ __forceinline__ void cp16(uint32_t dst, const void* src) {
    asm volatile("cp.async.cg.shared.global [%0], [%1], 16;"
                 :: "r"(dst), "l"(src));
}

__device__ __forceinline__ uint32_t sw_off(int row, int kc) {
    return (uint32_t)(row * 64 + ((kc ^ ((row >> 1) & 3)) << 4));
}

// ========================= fp16x2 HMMA GEMM, 64x128 tile ====================
// D = (Ah+Al) @ Bh^T + bias. Tile 64x128 (MxN), BK=32, 8 warps (warp tile
// 32x32), 3 CTAs/SM via __launch_bounds__(256,3). 3-stage cp.async pipeline.
#define BKQ 32
#define NSTAGE 3
#define STAGE_BYTES 16384
#define OFF_AH 0
#define OFF_AL 4096
#define OFF_BH 8192
#define GEMM_SMEM (NSTAGE * STAGE_BYTES)

__global__ __launch_bounds__(256, 3) void gemm_fp16x2_kernel(
    const __half* __restrict__ Ah, const __half* __restrict__ Al,
    const __half* __restrict__ Bh,
    const float* __restrict__ bias, float* __restrict__ Cout,
    int M, int N, int K)
{
    extern __shared__ char smem[];
    const uint32_t sb = smem_u32(smem);
    const int tid  = threadIdx.x;
    const int brow = blockIdx.y * 64;
    const int bcol = blockIdx.x * 128;
    const int wid  = tid >> 5, lane = tid & 31;
    const int wm   = wid >> 2, wn = wid & 3;        // 2 x 4 warp grid

    const int lr = tid >> 2, lc = tid & 3;           // 64 rows x 4 chunks

    const int a_row = (lane & 7) + ((lane >> 3) & 1) * 8;
    const int a_kc  = lane >> 4;
    const int b_row = (lane & 7) + ((lane >> 4) & 1) * 8;
    const int b_kc  = (lane >> 3) & 1;

    float acc[2][4][4];
#pragma unroll
    for (int i = 0; i < 2; i++)
#pragma unroll
        for (int j = 0; j < 4; j++)
#pragma unroll
            for (int q = 0; q < 4; q++) acc[i][j][q] = 0.0f;

    auto issue_stage = [&](int stage, int k0) {
        uint32_t st = sb + stage * STAGE_BYTES;
        uint32_t o = sw_off(lr, lc);
        size_t ga = (size_t)(brow + lr) * K + k0 + lc * 8;
        cp16(st + OFF_AH + o, Ah + ga);
        cp16(st + OFF_AL + o, Al + ga);
#pragma unroll
        for (int p = 0; p < 2; ++p) {
            int r = lr + p * 64;
            size_t gb = (size_t)(bcol + r) * K + k0 + lc * 8;
            cp16(st + OFF_BH + sw_off(r, lc), Bh + gb);
        }
        asm volatile("cp.async.commit_group;");
    };

    const int niter = K / BKQ;
    issue_stage(0, 0);
    if (niter > 1) issue_stage(1, BKQ);

    for (int it = 0; it < niter; ++it) {
        if (it + 1 < niter) asm volatile("cp.async.wait_group 1;");
        else                asm volatile("cp.async.wait_group 0;");
        __syncthreads();
        if (it + 2 < niter) issue_stage((it + 2) % NSTAGE, (it + 2) * BKQ);

        const uint32_t st = sb + (it % NSTAGE) * STAGE_BYTES;

#pragma unroll
        for (int ks = 0; ks < 2; ++ks) {
            uint32_t ah[2][4], al[2][4], bh[4][2];
#pragma unroll
            for (int pr = 0; pr < 2; ++pr) {
                int row = wn * 32 + pr * 16 + b_row;
                uint32_t ad = st + OFF_BH + sw_off(row, ks * 2 + b_kc);
                ldsm4(bh[2 * pr][0], bh[2 * pr][1],
                      bh[2 * pr + 1][0], bh[2 * pr + 1][1], ad);
            }
#pragma unroll
            for (int mt = 0; mt < 2; ++mt) {
                int row = wm * 32 + mt * 16 + a_row;
                uint32_t ad = st + OFF_AH + sw_off(row, ks * 2 + a_kc);
                ldsm4(ah[mt][0], ah[mt][1], ah[mt][2], ah[mt][3], ad);
            }
#pragma unroll
            for (int mt = 0; mt < 2; ++mt)
#pragma unroll
                for (int nt = 0; nt < 4; ++nt)
                    mma16816f16(acc[mt][nt], ah[mt], bh[nt]);
#pragma unroll
            for (int mt = 0; mt < 2; ++mt) {
                int row = wm * 32 + mt * 16 + a_row;
                uint32_t ad = st + OFF_AL + sw_off(row, ks * 2 + a_kc);
                ldsm4(al[mt][0], al[mt][1], al[mt][2], al[mt][3], ad);
            }
#pragma unroll
            for (int mt = 0; mt < 2; ++mt)
#pragma unroll
                for (int nt = 0; nt < 4; ++nt)
                    mma16816f16(acc[mt][nt], al[mt], bh[nt]);
        }
    }

    const int gid = lane >> 2, tig = lane & 3;
#pragma unroll
    for (int mt = 0; mt < 2; ++mt) {
#pragma unroll
        for (int nt = 0; nt < 4; ++nt) {
            int row = brow + wm * 32 + mt * 16 + gid;
            int col = bcol + wn * 32 + nt * 8 + tig * 2;
            float b0 = bias[col], b1 = bias[col + 1];
            float2 v0 = make_float2(acc[mt][nt][0] + b0, acc[mt][nt][1] + b1);
            float2 v1 = make_float2(acc[mt][nt][2] + b0, acc[mt][nt][3] + b1);
            *(float2*)(Cout + (size_t)row * N + col) = v0;
            *(float2*)(Cout + (size_t)(row + 8) * N + col) = v1;
        }
    }
}

// ========================= fp32 -> fp16 hi/lo split =========================
__global__ void split_kernel(const float* __restrict__ in,
                             __half* __restrict__ h,
                             __half* __restrict__ l, int n)
{
    int i = blockIdx.x * blockDim.x + threadIdx.x;
    if (i < n) {
        float v = in[i];
        __half hh = __float2half(v);
        h[i] = hh;
        l[i] = __float2half(v - __half2float(hh));
    }
}

// ============ weight transpose to fp16: W[K][N] -> Wt[N][K] =================
__global__ void wsplit_t_kernel(const float* __restrict__ W,
                                __half* __restrict__ Wth, int K, int N)
{
    __shared__ float t[32][33];
    const int n0 = blockIdx.x * 32, k0 = blockIdx.y * 32;
    const int tx = threadIdx.x, ty = threadIdx.y;
#pragma unroll
    for (int j = 0; j < 4; ++j)
        t[ty + j * 8][tx] = W[(size_t)(k0 + ty + j * 8) * N + n0 + tx];
    __syncthreads();
#pragma unroll
    for (int j = 0; j < 4; ++j) {
        int nn = ty + j * 8;
        Wth[(size_t)(n0 + nn) * K + k0 + tx] = __float2half(t[tx][nn]);
    }
}

// ============ single-pass top-4 + rowsum (branchless scalar regs) ===========
__device__ __forceinline__ void ins4(float& v0, int& i0, float& v1, int& i1,
                                     float& v2, int& i2, float& v3, int& i3,
                                     float val, int idx)
{
    bool b0 = (val > v0) | ((val == v0) & (idx < i0));
    bool b1 = (val > v1) | ((val == v1) & (idx < i1));
    bool b2 = (val > v2) | ((val == v2) & (idx < i2));
    bool b3 = (val > v3) | ((val == v3) & (idx < i3));
    v3 = b3 ? (b2 ? v2 : val) : v3;  i3 = b3 ? (b2 ? i2 : idx) : i3;
    v2 = b2 ? (b1 ? v1 : val) : v2;  i2 = b2 ? (b1 ? i1 : idx) : i2;
    v1 = b1 ? (b0 ? v0 : val) : v1;  i1 = b1 ? (b0 ? i0 : idx) : i1;
    v0 = b0 ? val : v0;              i0 = b0 ? idx : i0;
}

__global__ void topk_kernel(const float* __restrict__ tau,
                            int* __restrict__ topk,
                            float* __restrict__ rowsum, int T)
{
    const int row  = blockIdx.x;
    const int tid  = threadIdx.x;
    const int lane = tid & 31, wid = tid >> 5;
    const float* tr = tau + (size_t)row * T;

    float v0 = -INFINITY, v1 = -INFINITY, v2 = -INFINITY, v3 = -INFINITY;
    int   i0 = 0x7FFFFFFF, i1 = 0x7FFFFFFF, i2 = 0x7FFFFFFF, i3 = 0x7FFFFFFF;
    float s = 0.0f;

    for (int i = tid; i < T; i += 256) {
        float val = tr[i];
        s += val;
        ins4(v0, i0, v1, i1, v2, i2, v3, i3, val, i);
    }

#pragma unroll
    for (int off = 16; off > 0; off >>= 1) {
        s += __shfl_xor_sync(0xFFFFFFFFu, s, off);
        float w0 = __shfl_xor_sync(0xFFFFFFFFu, v0, off);
        int   j0 = __shfl_xor_sync(0xFFFFFFFFu, i0, off);
        float w1 = __shfl_xor_sync(0xFFFFFFFFu, v1, off);
        int   j1 = __shfl_xor_sync(0xFFFFFFFFu, i1, off);
        float w2 = __shfl_xor_sync(0xFFFFFFFFu, v2, off);
        int   j2 = __shfl_xor_sync(0xFFFFFFFFu, i2, off);
        float w3 = __shfl_xor_sync(0xFFFFFFFFu, v3, off);
        int   j3 = __shfl_xor_sync(0xFFFFFFFFu, i3, off);
        ins4(v0, i0, v1, i1, v2, i2, v3, i3, w0, j0);
        ins4(v0, i0, v1, i1, v2, i2, v3, i3, w1, j1);
        ins4(v0, i0, v1, i1, v2, i2, v3, i3, w2, j2);
        ins4(v0, i0, v1, i1, v2, i2, v3, i3, w3, j3);
    }

    __shared__ float wv[8][4];
    __shared__ int   wi[8][4];
    __shared__ float ws[8];
    if (lane == 0) {
        wv[wid][0] = v0; wv[wid][1] = v1; wv[wid][2] = v2; wv[wid][3] = v3;
        wi[wid][0] = i0; wi[wid][1] = i1; wi[wid][2] = i2; wi[wid][3] = i3;
        ws[wid] = s;
    }
    __syncthreads();

    if (tid == 0) {
        float sum = ws[0];
#pragma unroll
        for (int w = 1; w < 8; ++w) {
            sum += ws[w];
            ins4(v0, i0, v1, i1, v2, i2, v3, i3, wv[w][0], wi[w][0]);
            ins4(v0, i0, v1, i1, v2, i2, v3, i3, wv[w][1], wi[w][1]);
            ins4(v0, i0, v1, i1, v2, i2, v3, i3, wv[w][2], wi[w][2]);
            ins4(v0, i0, v1, i1, v2, i2, v3, i3, wv[w][3], wi[w][3]);
        }
        rowsum[row] = sum;
        int4 r = make_int4(i0, i1, i2, i3);
        *(int4*)(topk + row * TOPK) = r;
    }
}

// ================= sparse attention core (float2 vectorized) ================
__global__ void attn_kernel(const float* __restrict__ qkv,
                            const float* __restrict__ tau,
                            const int* __restrict__ topk,
                            __half* __restrict__ aoh,
                            __half* __restrict__ aol,
                            float* __restrict__ sig3,
                            float* __restrict__ sigsum,
                            int T, int C)
{
    const int row = blockIdx.x;
    const int b   = row / T;
    const int h   = threadIdx.x >> 5;
    const int l   = threadIdx.x & 31;
    const int C3  = 3 * C;

    __shared__ int   sidx[TOPK];
    __shared__ float sbias[TOPK];
    __shared__ float satt[NUM_HEADS][TOPK];

    if (threadIdx.x < TOPK) {
        int id = topk[row * TOPK + threadIdx.x];
        sidx[threadIdx.x]  = id;
        sbias[threadIdx.x] = GAMMA * logf(tau[(size_t)row * T + id] + 1e-8f);
    }
    __syncthreads();

    const float* qrow = qkv + (size_t)row * C3 + h * 64;
    const float2 q01 = *(const float2*)(qrow + 2 * l);

    float logit[TOPK];
#pragma unroll
    for (int j = 0; j < TOPK; j++) {
        const float* krow = qkv + (size_t)(b * T + sidx[j]) * C3 + C + h * 64;
        float2 kk = *(const float2*)(krow + 2 * l);
        float p = q01.x * kk.x + q01.y * kk.y;
#pragma unroll
        for (int off = 16; off > 0; off >>= 1)
            p += __shfl_xor_sync(0xFFFFFFFFu, p, off);
        logit[j] = p * 0.125f + sbias[j];
    }

    float m = fmaxf(fmaxf(logit[0], logit[1]), fmaxf(logit[2], logit[3]));
    float e[TOPK], den = 0.0f;
#pragma unroll
    for (int j = 0; j < TOPK; j++) { e[j] = expf(logit[j] - m); den += e[j]; }
    float inv = 1.0f / den;
    float a[TOPK];
#pragma unroll
    for (int j = 0; j < TOPK; j++) a[j] = e[j] * inv;

    float o0 = 0.0f, o1 = 0.0f;
#pragma unroll
    for (int j = 0; j < TOPK; j++) {
        const float* vrow = qkv + (size_t)(b * T + sidx[j]) * C3 + 2 * C + h * 64;
        float2 vv = *(const float2*)(vrow + 2 * l);
        o0 = fmaf(a[j], vv.x, o0);
        o1 = fmaf(a[j], vv.y, o1);
    }
    {
        size_t base = (size_t)row * C + h * 64 + 2 * l;
        __half h0 = __float2half(o0);
        __half h1 = __float2half(o1);
        __half2 hv; hv.x = h0; hv.y = h1;
        *(__half2*)(aoh + base) = hv;
        __half2 lv;
        lv.x = __float2half(o0 - __half2float(h0));
        lv.y = __float2half(o1 - __half2float(h1));
        *(__half2*)(aol + base) = lv;
    }

    if (l == 0) {
#pragma unroll
        for (int j = 0; j < TOPK; j++) satt[h][j] = a[j];
    }
    __syncthreads();

    if (threadIdx.x == 0) {
        float ss = 0.0f;
#pragma unroll
        for (int j = 0; j < TOPK; j++) {
            float sgn = 0.0f;
#pragma unroll
            for (int hh = 0; hh < NUM_HEADS; hh++) sgn += satt[hh][j];
            sgn *= (1.0f / NUM_HEADS);
            float s3 = sgn * sgn * sgn;
            sig3[row * TOPK + j] = s3;
            ss += s3;
        }
        sigsum[row] = ss;
    }
}

// ============== tau EMA: fused branchless stream + in-block fixup ===========
__global__ void tau_kernel(const float* __restrict__ tau,
                           const int* __restrict__ topk,
                           const float* __restrict__ sig3,
                           const float* __restrict__ rowsum,
                           const float* __restrict__ sigsum,
                           float* __restrict__ tau_out, int T)
{
    const int row = blockIdx.x;
    const float keep = 1.0f - RHO;
    const float denom = keep * rowsum[row] + sigsum[row] + 1e-8f;
    const float ki  = keep / denom;
    const float inv = 1.0f / denom;

    const float4* tr = (const float4*)(tau + (size_t)row * T);
    float4* to = (float4*)(tau_out + (size_t)row * T);
    const int n4 = T >> 2;
    for (int i = threadIdx.x; i < n4; i += blockDim.x) {
        float4 v = tr[i];
        v.x = fminf(v.x * ki, TAU_CLIP);
        v.y = fminf(v.y * ki, TAU_CLIP);
        v.z = fminf(v.z * ki, TAU_CLIP);
        v.w = fminf(v.w * ki, TAU_CLIP);
        to[i] = v;
    }
    __syncthreads();

    if (threadIdx.x < TOPK) {
        int s = topk[row * TOPK + threadIdx.x];
        float v = keep * tau[(size_t)row * T + s] + sig3[row * TOPK + threadIdx.x];
        tau_out[(size_t)row * T + s] = fminf(v * inv, TAU_CLIP);
    }
}

// ========================= launch ===========================================
extern "C" void kernel_launch(void* const* d_in, const int* in_sizes, int n_in,
                              void* d_out, int out_size)
{
    const float* x     = (const float*)d_in[0];
    const float* tau   = (const float*)d_in[1];
    const float* Wqkv  = (const float*)d_in[2];
    const float* bqkv  = (const float*)d_in[3];
    const float* Wproj = (const float*)d_in[4];
    const float* bproj = (const float*)d_in[5];

    const int C  = in_sizes[5];                 // 512
    const int BT = in_sizes[0] / C;             // 4096
    const int T  = in_sizes[1] / BT;            // 2048
    const int C3 = 3 * C;

    float* out_main = (float*)d_out;
    float* tau_out  = out_main + (size_t)BT * C;

    float* qkv;    cudaGetSymbolAddress((void**)&qkv,  g_qkv);
    __half *xh, *xl, *aoh, *aol, *wqh, *wph;
    cudaGetSymbolAddress((void**)&xh,  g_xh);
    cudaGetSymbolAddress((void**)&xl,  g_xl);
    cudaGetSymbolAddress((void**)&aoh, g_aoh);
    cudaGetSymbolAddress((void**)&aol, g_aol);
    cudaGetSymbolAddress((void**)&wqh, g_wqh);
    cudaGetSymbolAddress((void**)&wph, g_wph);
    int*   topk;   cudaGetSymbolAddress((void**)&topk,   g_topk);
    float* sig3;   cudaGetSymbolAddress((void**)&sig3,   g_sig3);
    float* rowsum; cudaGetSymbolAddress((void**)&rowsum, g_rowsum);
    float* sigsum; cudaGetSymbolAddress((void**)&sigsum, g_sigsum);

    // one-time setup: smem attribute + side stream + fork/join events
    static cudaStream_t s1 = nullptr;
    static cudaEvent_t evFork = nullptr, evSide = nullptr,
                       evAttn = nullptr, evTau = nullptr;
    if (s1 == nullptr) {
        cudaFuncSetAttribute(gemm_fp16x2_kernel,
                             cudaFuncAttributeMaxDynamicSharedMemorySize,
                             GEMM_SMEM);
        cudaStreamCreateWithFlags(&s1, cudaStreamNonBlocking);
        cudaEventCreateWithFlags(&evFork, cudaEventDisableTiming);
        cudaEventCreateWithFlags(&evSide, cudaEventDisableTiming);
        cudaEventCreateWithFlags(&evAttn, cudaEventDisableTiming);
        cudaEventCreateWithFlags(&evTau,  cudaEventDisableTiming);
    }

    // ---- fork: side stream runs topk + Wproj prep, overlapping qkv GEMM ----
    cudaEventRecord(evFork, 0);
    cudaStreamWaitEvent(s1, evFork, 0);
    topk_kernel<<<BT, 256, 0, s1>>>(tau, topk, rowsum, T);
    {
        dim3 tb(32, 8);
        wsplit_t_kernel<<<dim3(C / 32, C / 32), tb, 0, s1>>>(Wproj, wph, C, C);
    }
    cudaEventRecord(evSide, s1);

    // ---- main stream: operand prep + qkv GEMM ----
    {
        int n = BT * C;
        split_kernel<<<(n + 255) / 256, 256>>>(x, xh, xl, n);
        dim3 tb(32, 8);
        wsplit_t_kernel<<<dim3(C3 / 32, C / 32), tb>>>(Wqkv, wqh, C, C3);
    }
    {
        dim3 grid(C3 / 128, BT / 64);
        gemm_fp16x2_kernel<<<grid, 256, GEMM_SMEM>>>(xh, xl, wqh,
                                                     bqkv, qkv, BT, C3, C);
    }

    // ---- join: attention needs qkv (main) + topk (side) ----
    cudaStreamWaitEvent(0, evSide, 0);
    attn_kernel<<<BT, 256>>>(qkv, tau, topk, aoh, aol, sig3, sigsum, T, C);
    cudaEventRecord(evAttn, 0);

    // ---- fork again: tau update (DRAM-bound) overlaps proj GEMM (tensor) ----
    cudaStreamWaitEvent(s1, evAttn, 0);
    tau_kernel<<<BT, 256, 0, s1>>>(tau, topk, sig3, rowsum, sigsum, tau_out, T);
    cudaEventRecord(evTau, s1);

    // ---- main stream: proj GEMM ----
    {
        dim3 grid(C / 128, BT / 64);
        gemm_fp16x2_kernel<<<grid, 256, GEMM_SMEM>>>(aoh, aol, wph,
                                                     bproj, out_main, BT, C, C);
    }
    // ---- final join so all captured work ends on the origin stream ----
    cudaStreamWaitEvent(0, evTau, 0);
}